// round 14
// baseline (speedup 1.0000x reference)
#include <cuda_runtime.h>
#include <cuda_fp16.h>
#include <math.h>
#include <stdint.h>

#define BB 64
#define NN 64
#define HH 128
#define EFD 32
#define LN_EPS 1e-5f
#define CUT 10.0f
#define ASTR 136   // Ah row stride (words)
#define BSTR 40    // Bh row stride (words)

// ---------------- device scratch (no runtime allocation) ----------------
static __device__ __half g_maskh[BB*NN*NN*HH]; // 64 MB fp16 mask
static __device__ float g_ea  [BB*NN*NN];
static __device__ float g_ev  [BB*NN*NN*3];
static __device__ float g_s   [BB*NN*HH];
static __device__ float g_sn  [BB*NN*HH];
static __device__ float g_t   [BB*NN*HH];
static __device__ float g_v   [BB*NN*3*HH];
static __device__ float g_vq  [BB*NN*3*HH];
static __device__ float g_vk  [BB*NN*3*HH];
static __device__ float g_sl  [BB*NN*HH];
static __device__ float g_P   [BB*NN*3*256];   // P_i = V_i @ Wd1[0:128]
static __device__ unsigned gW1h3[256*64];      // Wd1 dir3 rows packed fp16 (x64), k-pair permuted
static __device__ unsigned gW2h [128*128];     // Wd2 packed fp16, k-pair permuted

// k-pair permutation within each 8-group: [0,4,1,5,2,6,3,7] -> pairs (t,t+4) adjacent
__device__ __forceinline__ int ast(int kp){
    return (kp & ~7) | (((kp & 3) << 1) | ((kp >> 2) & 1));
}

// ---- fast exp2 poly ----
__device__ __forceinline__ float exp2_poly(float f){
    float p = 1.3333558e-3f;
    p = fmaf(p, f, 9.6181291e-3f);
    p = fmaf(p, f, 5.5504109e-2f);
    p = fmaf(p, f, 2.4022651e-1f);
    p = fmaf(p, f, 6.9314718e-1f);
    p = fmaf(p, f, 1.0f);
    return p;
}
__device__ __forceinline__ float exp2n_f(float t){
    t = fmaxf(t, -126.0f);
    float fn = t + 12582912.0f;
    float n  = fn - 12582912.0f;
    float f  = t - n;
    int ni = __float_as_int(fn) - 0x4B400000;
    float scale = __int_as_float((ni + 127) << 23);
    return exp2_poly(f) * scale;
}
// silu: poly exp2 on FMA pipe + MUFU rcp (pipes overlap)
__device__ __forceinline__ float silu_f(float x){
    float t = x * (-1.442695041f);
    t = fminf(fmaxf(t, -126.0f), 126.0f);
    float fn = t + 12582912.0f;
    float n  = fn - 12582912.0f;
    float f  = t - n;
    int ni = __float_as_int(fn) - 0x4B400000;
    float scale = __int_as_float((ni + 127) << 23);
    float e = exp2_poly(f) * scale;   // e^{-x}
    float d = 1.0f + e;
    float y;
    asm("rcp.approx.f32 %0, %1;" : "=f"(y) : "f"(d));
    return x * y;
}

// ---- fp16 pack: {low16 = f16(f0), high16 = f16(f1)} ----
__device__ __forceinline__ unsigned half_pack(float f0, float f1){
    unsigned p;
    asm("cvt.rn.f16x2.f32 %0, %1, %2;" : "=r"(p) : "f"(f1), "f"(f0));
    return p;
}

// ---- mma.sync fp16 m16n8k16, fp32 accumulate ----
__device__ __forceinline__ void mma16h(float* c, const unsigned* a, unsigned b0, unsigned b1){
    asm("mma.sync.aligned.m16n8k16.row.col.f32.f16.f16.f32 "
        "{%0,%1,%2,%3},{%4,%5,%6,%7},{%8,%9},{%0,%1,%2,%3};"
        : "+f"(c[0]), "+f"(c[1]), "+f"(c[2]), "+f"(c[3])
        : "r"(a[0]), "r"(a[1]), "r"(a[2]), "r"(a[3]), "r"(b0), "r"(b1));
}
// ---- mma.sync fp16 m16n8k16, fp16 accumulate (2x rate, packed half2 accum) ----
__device__ __forceinline__ void mma16hh(unsigned* c, const unsigned* a, unsigned b0, unsigned b1){
    asm("mma.sync.aligned.m16n8k16.row.col.f16.f16.f16.f16 "
        "{%0,%1},{%2,%3,%4,%5},{%6,%7},{%0,%1};"
        : "+r"(c[0]), "+r"(c[1])
        : "r"(a[0]), "r"(a[1]), "r"(a[2]), "r"(a[3]), "r"(b0), "r"(b1));
}

// block reduction for 128 threads (4 warps)
__device__ __forceinline__ float blkred128(float v, volatile float* red){
    #pragma unroll
    for (int o = 16; o > 0; o >>= 1) v += __shfl_xor_sync(0xffffffffu, v, o);
    if ((threadIdx.x & 31) == 0) red[threadIdx.x >> 5] = v;
    __syncthreads();
    v = red[0] + red[1] + red[2] + red[3];
    __syncthreads();
    return v;
}

// ---------------- K0: convert weights to packed fp16 (k-pair permuted) ----------------
__global__ void k_whalf(const float* __restrict__ Wd1, const float* __restrict__ Wd2){
    int n = blockIdx.x, kp = threadIdx.x;
    if (n < 256){
        if (kp < 64){
            float f0 = Wd1[(128 + 2*kp    )*256 + n] * 64.0f;
            float f1 = Wd1[(128 + 2*kp + 1)*256 + n] * 64.0f;
            gW1h3[n*64 + ast(kp)] = half_pack(f0, f1);
        }
    } else {
        int n2 = n - 256;
        float f0 = Wd2[(2*kp  )*128 + n2];
        float f1 = Wd2[(2*kp+1)*128 + n2];
        gW2h[n2*128 + ast(kp)] = half_pack(f0, f1);
    }
}

// ---------------- K0b: P_i = V_i @ Wd1[0:128]  (3 x 256 per atom, fp32) ----------------
__global__ void k_p(const float* __restrict__ Wd1){
    int bi = blockIdx.x, n = threadIdx.x;
    __shared__ float vs[3*HH];
    for (int r = n; r < 3*HH; r += 256) vs[r] = g_v[bi*3*HH + r];
    __syncthreads();
    float p0 = 0.f, p1 = 0.f, p2 = 0.f;
    #pragma unroll 4
    for (int k = 0; k < HH; k++){
        float w = Wd1[k*256 + n];
        p0 = fmaf(vs[k],        w, p0);
        p1 = fmaf(vs[HH + k],   w, p1);
        p2 = fmaf(vs[2*HH + k], w, p2);
    }
    g_P[bi*768 + n]       = p0;
    g_P[bi*768 + 256 + n] = p1;
    g_P[bi*768 + 512 + n] = p2;
}

// ---------------- K1: geometry + RBF filter mask (256 threads) ----------------
__global__ void k_geom(const int* __restrict__ z, const float* __restrict__ pos,
                       const float* __restrict__ Wef, const float* __restrict__ bef){
    int blk = blockIdx.x;
    int b = blk >> 6, i = blk & 63;
    int t = threadIdx.x;               // 256

    __shared__ float pos_s[NN][3];
    __shared__ int   z_s[NN];
    __shared__ float d_s[NN], ea_s[NN];
    __shared__ float ef_s[NN][EFD];
    __shared__ float Wef_s[EFD*HH];
    __shared__ float bef_s[HH];

    for (int r = t; r < EFD*HH; r += 256) Wef_s[r] = Wef[r];
    if (t < HH) bef_s[t] = bef[t];
    if (t < NN){
        z_s[t] = z[b*NN + t];
        pos_s[t][0] = pos[(b*NN + t)*3 + 0];
        pos_s[t][1] = pos[(b*NN + t)*3 + 1];
        pos_s[t][2] = pos[(b*NN + t)*3 + 2];
    }
    __syncthreads();

    if (t < NN){
        int j = t;
        float dx = pos_s[j][0] - pos_s[i][0];
        float dy = pos_s[j][1] - pos_s[i][1];
        float dz = pos_s[j][2] - pos_s[i][2];
        float d2 = dx*dx + dy*dy + dz*dz;
        float d  = sqrtf(fmaxf(d2, 1e-12f));
        d_s[j] = d;
        bool pair = (z_s[i] != 0) && (z_s[j] != 0) && (j != i);
        float ea = (pair && d < CUT) ? 0.5f*(cosf(3.14159265358979323846f * d / CUT) + 1.0f) : 0.0f;
        ea_s[j] = ea;
        g_ea[blk*NN + j] = ea;
        float inv = 1.0f / d;
        g_ev[(blk*NN + j)*3 + 0] = pair ? dx*inv : 0.0f;
        g_ev[(blk*NN + j)*3 + 1] = pair ? dy*inv : 0.0f;
        g_ev[(blk*NN + j)*3 + 2] = pair ? dz*inv : 0.0f;
    }
    __syncthreads();

    const float step = CUT / (float)(EFD - 1);
    for (int r = t; r < NN*EFD; r += 256){
        int j = r >> 5, k = r & 31;
        float dd = d_s[j] - step*(float)k;
        ef_s[j][k] = exp2n_f(-14.4269504089f * dd * dd);
    }
    __syncthreads();

    int hp = t & 63, jh = t >> 6;
    int h0 = 2*hp;
    __half2* mrow = (__half2*)(g_maskh + (size_t)blk*NN*HH);
    for (int jj = 0; jj < 16; jj++){
        int j = jh*16 + jj;
        float a0 = bef_s[h0], a1 = bef_s[h0+1];
        #pragma unroll
        for (int k = 0; k < EFD; k++){
            float e = ef_s[j][k];
            a0 = fmaf(e, Wef_s[k*HH + h0],     a0);
            a1 = fmaf(e, Wef_s[k*HH + h0 + 1], a1);
        }
        float ea = ea_s[j];
        float2 m; m.x = silu_f(a0) * ea; m.y = silu_f(a1) * ea;
        mrow[j*64 + hp] = __float22half2_rn(m);
    }
}

// ---------------- K2a: s = emb[z];  sn = LN(emb2[z]) ----------------
__global__ void k_embed(const int* __restrict__ z, const float* __restrict__ emb_w,
                        const float* __restrict__ emb2_w){
    int a = blockIdx.x, h = threadIdx.x;
    __shared__ float red[4];
    int zi = z[a];
    g_s[a*HH + h] = emb_w[zi*HH + h];
    float x = emb2_w[zi*HH + h];
    float s1 = blkred128(x, red);
    float s2 = blkred128(x*x, red);
    float m = s1 * (1.0f/HH);
    float var = fmaxf(s2 * (1.0f/HH) - m*m, 0.0f);
    g_sn[a*HH + h] = (x - m) * rsqrtf(var + LN_EPS);
}

// ---------------- K2b / K6b: s += mask @ src (8 i-rows x h-half per block) ----------------
__global__ void k_gather(int sel){
    int blk = blockIdx.x;              // ((b*8 + ig)*2 + hh)
    int hh = blk & 1;
    int ig = (blk >> 1) & 7;
    int b  = blk >> 4;
    int i0 = ig * 8;
    int t  = threadIdx.x;              // 256
    int h2 = t & 31;                   // half2 col within half (h = hh*64 + 2*h2)
    int rg = t >> 5;                   // 0..7 i-row
    const float* src = sel ? g_sl : g_sn;
    __shared__ float srcs[NN*64];      // 16 KB
    const float* sb = src + b*NN*HH + hh*64;
    for (int r = t; r < NN*64; r += 256){
        int j = r >> 6, c = r & 63;
        srcs[r] = sb[j*HH + c];
    }
    __syncthreads();
    const __half2* m0 = (const __half2*)(g_maskh + (size_t)((b*NN + i0 + rg)*NN)*HH) + hh*32;
    float2 a0 = make_float2(0.f, 0.f);
    #pragma unroll 8
    for (int j = 0; j < NN; j++){
        float2 sv = *(const float2*)&srcs[j*64 + 2*h2];
        float2 q0 = __half22float2(m0[j*64 + h2]);
        a0.x = fmaf(q0.x, sv.x, a0.x); a0.y = fmaf(q0.y, sv.y, a0.y);
    }
    float2* sp0 = (float2*)&g_s[(b*NN + i0 + rg)*HH + hh*64 + 2*h2];
    float2 s0 = *sp0; s0.x += a0.x; s0.y += a0.y; *sp0 = s0;
}

// ---------------- K3 / K6a: dst = silu(LN(s @ W + bias)), 8 atoms per block ----------------
__global__ void k_lin(const float* __restrict__ W, const float* __restrict__ bias,
                      int dst_sel){
    int blk = blockIdx.x;
    int h = threadIdx.x;               // 128
    __shared__ float xs[8][HH];
    __shared__ float ys[8][HH];
    __shared__ float mm[8], rr[8];
    for (int r = h; r < 8*HH; r += 128) ((float*)xs)[r] = g_s[blk*8*HH + r];
    __syncthreads();
    float bh = bias[h];
    float acc[8];
    #pragma unroll
    for (int a = 0; a < 8; a++) acc[a] = bh;
    #pragma unroll 4
    for (int k = 0; k < HH; k++){
        float w = W[k*HH + h];
        #pragma unroll
        for (int a = 0; a < 8; a++) acc[a] = fmaf(xs[a][k], w, acc[a]);
    }
    #pragma unroll
    for (int a = 0; a < 8; a++) ys[a][h] = acc[a];
    __syncthreads();
    {
        int w = h >> 5, l = h & 31;
        #pragma unroll
        for (int aa = 0; aa < 2; aa++){
            int a = w + aa*4;
            float s1 = 0.f, s2 = 0.f;
            #pragma unroll
            for (int c = l; c < HH; c += 32){ float v = ys[a][c]; s1 += v; s2 += v*v; }
            #pragma unroll
            for (int o = 16; o > 0; o >>= 1){
                s1 += __shfl_xor_sync(0xffffffffu, s1, o);
                s2 += __shfl_xor_sync(0xffffffffu, s2, o);
            }
            if (l == 0){
                float m = s1 * (1.0f/HH);
                float var = fmaxf(s2 * (1.0f/HH) - m*m, 0.0f);
                mm[a] = m; rr[a] = rsqrtf(var + LN_EPS);
            }
        }
    }
    __syncthreads();
    float* dst = dst_sel ? g_sl : g_t;
    #pragma unroll
    for (int a = 0; a < 8; a++)
        dst[(blk*8 + a)*HH + h] = silu_f((ys[a][h] - mm[a]) * rr[a]);
}

// ---------------- K4a: v = sum_j mask*t*ev (4 i-rows/block, half2 loads) ----------------
__global__ void k_v(){
    int blk = blockIdx.x;
    int b  = blk >> 4;
    int i0 = (blk & 15) * 4;
    int t  = threadIdx.x;              // 256
    int h2 = t & 63;
    int rg = t >> 6;
    __shared__ float ts[NN*HH];
    __shared__ float evl[4][NN*3];
    const float* tb = g_t + b*NN*HH;
    for (int r = t; r < NN*HH; r += 256) ts[r] = tb[r];
    for (int r = t; r < 4*NN*3; r += 256) ((float*)evl)[r] = g_ev[(b*NN + i0)*NN*3 + r];
    __syncthreads();
    const __half2* m0 = (const __half2*)(g_maskh + (size_t)((b*NN + i0 + rg)*NN)*HH);
    float a00 = 0.f, a01 = 0.f, a10 = 0.f, a11 = 0.f, a20 = 0.f, a21 = 0.f;
    #pragma unroll 4
    for (int j = 0; j < NN; j++){
        float2 tv = *(const float2*)&ts[j*HH + 2*h2];
        float2 mq = __half22float2(m0[j*64 + h2]);
        float m0v = mq.x * tv.x, m1v = mq.y * tv.y;
        float e0 = evl[rg][j*3+0], e1 = evl[rg][j*3+1], e2 = evl[rg][j*3+2];
        a00 = fmaf(m0v, e0, a00); a01 = fmaf(m1v, e0, a01);
        a10 = fmaf(m0v, e1, a10); a11 = fmaf(m1v, e1, a11);
        a20 = fmaf(m0v, e2, a20); a21 = fmaf(m1v, e2, a21);
    }
    int base = (b*NN + i0 + rg)*3;
    *(float2*)&g_v[(base + 0)*HH + 2*h2] = make_float2(a00, a01);
    *(float2*)&g_v[(base + 1)*HH + 2*h2] = make_float2(a10, a11);
    *(float2*)&g_v[(base + 2)*HH + 2*h2] = make_float2(a20, a21);
}

// ---------------- K4b: vq = v@Wq, vk = v@Wk (8 rows per block) ----------------
__global__ void k_vqk(const float* __restrict__ Wq, const float* __restrict__ Wk){
    int blk = blockIdx.x;
    int h = threadIdx.x;
    __shared__ float vs[8][HH];
    for (int r = h; r < 8*HH; r += 128) ((float*)vs)[r] = g_v[blk*8*HH + r];
    __syncthreads();
    float aq[8], ak[8];
    #pragma unroll
    for (int r = 0; r < 8; r++){ aq[r] = 0.f; ak[r] = 0.f; }
    #pragma unroll 4
    for (int k = 0; k < HH; k++){
        float wq = Wq[k*HH + h];
        float wk = Wk[k*HH + h];
        #pragma unroll
        for (int r = 0; r < 8; r++){
            float v = vs[r][k];
            aq[r] = fmaf(v, wq, aq[r]);
            ak[r] = fmaf(v, wk, ak[r]);
        }
    }
    #pragma unroll
    for (int r = 0; r < 8; r++){
        g_vq[(blk*8 + r)*HH + h] = aq[r];
        g_vk[(blk*8 + r)*HH + h] = ak[r];
    }
}

// ---------------- K5: directional MLP (512 threads; GEMM1 fp16-accum) ----------------
// smem words: Ah 128*136=17408 | Bh 256*40=10240 | b1s 256 | b2s 128 = 28032 (112128 B)
#define SMEM_DIR_BYTES (28032*4)
__global__ void __launch_bounds__(512) k_dir(const float* __restrict__ bd1,
                                             const float* __restrict__ bd2){
    extern __shared__ unsigned smu[];
    unsigned* Ah = smu;                          // [e][kp], stride ASTR, k-pair permuted
    unsigned* Bh = smu + 17408;                  // staging [n][kp'], stride BSTR, permuted
    float* b1s = (float*)(smu + 27648);
    float* b2s = (float*)(smu + 27904);
    // pre-GEMM scratch overlaps Bh (dead before first staging store)
    float* eas = (float*)(Bh);                   // 128
    float* evs = (float*)(Bh + 128);             // 384
    float* vks = (float*)(Bh + 512);             // 768
    float* Ps  = (float*)(Bh + 1280);            // 1536

    int t = threadIdx.x, lane = t & 31, wid = t >> 5;
    int g = lane >> 2, tig = lane & 3;
    int bi0 = blockIdx.x * 2, bbase = bi0 & ~63;

    if (t < 256) b1s[t] = bd1[t];
    if (t < 128) b2s[t] = bd2[t];
    if (t < 128) eas[t] = g_ea[bi0*64 + t];
    for (int r = t; r < 384;  r += 512) evs[r] = g_ev[bi0*192 + r];
    for (int r = t; r < 768;  r += 512) vks[r] = g_vk[bi0*384 + r];
    for (int r = t; r < 1536; r += 512) Ps [r] = g_P [bi0*768 + r];
    __syncthreads();

    // build dir3 (scaled 1/64) -> Ah kp 0..63 (permuted positions)
    {
        int kp3 = t & 63, grp = t >> 6;          // grp 0..7
        int i  = grp & 1, jq = grp >> 1;         // jq 0..3: 16 j each
        int kk = 2*kp3;
        int astk = ast(kp3);
        float u0 = vks[i*384 + kk],     u1 = vks[i*384 + 128 + kk], u2 = vks[i*384 + 256 + kk];
        float w0 = vks[i*384 + kk + 1], w1 = vks[i*384 + 129 + kk], w2 = vks[i*384 + 257 + kk];
        for (int jj = 0; jj < 16; jj++){
            int j = jq*16 + jj;
            int e = i*64 + j;
            float ea = eas[e] * 0.015625f;
            const float* vq = g_vq + (bbase + j)*384 + kk;
            float2 q0 = *(const float2*)vq;
            float2 q1 = *(const float2*)(vq + 128);
            float2 q2 = *(const float2*)(vq + 256);
            float f0 = (q0.x*u0 + q1.x*u1 + q2.x*u2) * ea;
            float f1 = (q0.y*w0 + q1.y*w1 + q2.y*w2) * ea;
            Ah[e*ASTR + astk] = half_pack(f0, f1);
        }
    }

    int m0 = (wid & 3) * 32;                     // 4 m-groups x 32 rows
    int nh = wid >> 2;                           // 4 n-groups

    // init acc1 (fp16 packed) with dir2 low-rank contribution (GEMM1 cols nh*64 .. +63)
    unsigned acc1h[2][8][2];
    #pragma unroll
    for (int ms = 0; ms < 2; ms++){
        int ea_r = m0 + ms*16 + g;
        int eb_r = ea_r + 8;
        int ia = ea_r >> 6, ib = eb_r >> 6;
        float ca0 = evs[ea_r*3], ca1 = evs[ea_r*3+1], ca2 = evs[ea_r*3+2];
        float cb0 = evs[eb_r*3], cb1 = evs[eb_r*3+1], cb2 = evs[eb_r*3+2];
        float wa = eas[ea_r], wb = eas[eb_r];
        const float* Pa = Ps + ia*768;
        const float* Pb = Ps + ib*768;
        #pragma unroll
        for (int nt = 0; nt < 8; nt++){
            int c0 = nh*64 + nt*8 + 2*tig;
            float A0 = wa * (ca0*Pa[c0]   + ca1*Pa[256+c0]   + ca2*Pa[512+c0]);
            float A1 = wa * (ca0*Pa[c0+1] + ca1*Pa[256+c0+1] + ca2*Pa[512+c0+1]);
            float B0 = wb * (cb0*Pb[c0]   + cb1*Pb[256+c0]   + cb2*Pb[512+c0]);
            float B1 = wb * (cb0*Pb[c0+1] + cb1*Pb[256+c0+1] + cb2*Pb[512+c0+1]);
            acc1h[ms][nt][0] = half_pack(A0, A1);
            acc1h[ms][nt][1] = half_pack(B0, B1);
        }
    }

    // ===== GEMM1 (dir3 half): K=128, 2 chunks, fp16 accumulate =====
    {
        uint4 pf[4];
        #pragma unroll
        for (int q = 0; q < 4; q++){
            int r = t + q*512;
            pf[q] = *(const uint4*)&gW1h3[(r>>3)*64 + (r&7)*4];
        }
        __syncthreads();                 // scratch reads (build + init acc1) done
        #pragma unroll
        for (int q = 0; q < 4; q++){
            int r = t + q*512;
            *(uint4*)&Bh[(r>>3)*BSTR + (r&7)*4] = pf[q];
        }
        __syncthreads();
        for (int c = 0; c < 2; c++){
            if (c == 0){
                #pragma unroll
                for (int q = 0; q < 4; q++){
                    int r = t + q*512;
                    pf[q] = *(const uint4*)&gW1h3[(r>>3)*64 + 32 + (r&7)*4];
                }
            }
            #pragma unroll
            for (int ksl = 0; ksl < 4; ksl++){
                int kp0 = c*32 + ksl*8;
                int kb  = ksl*8;
                unsigned ah[2][4];
                #pragma unroll
                for (int ms = 0; ms < 2; ms++){
                    int r0 = m0 + ms*16;
                    uint2 pa0 = *(const uint2*)&Ah[(r0+g  )*ASTR + kp0 + 2*tig];
                    uint2 pa1 = *(const uint2*)&Ah[(r0+g+8)*ASTR + kp0 + 2*tig];
                    ah[ms][0] = pa0.x; ah[ms][1] = pa1.x;
                    ah[ms][2] = pa0.y; ah[ms][3] = pa1.y;
                }
                #pragma unroll
                for (int nt = 0; nt < 8; nt++){
                    int n0 = nh*64 + nt*8;
                    uint2 pb = *(const uint2*)&Bh[(n0+g)*BSTR + kb + 2*tig];
                    mma16hh(acc1h[0][nt], ah[0], pb.x, pb.y);
                    mma16hh(acc1h[1][nt], ah[1], pb.x, pb.y);
                }
            }
            __syncthreads();
            if (c == 0){
                #pragma unroll
                for (int q = 0; q < 4; q++){
                    int r = t + q*512;
                    *(uint4*)&Bh[(r>>3)*BSTR + (r&7)*4] = pf[q];
                }
                __syncthreads();
            }
        }
    }

    // epilogue1: h1 = silu(D1 + b1) packed back into Ah (permuted positions)
    #pragma unroll
    for (int ms = 0; ms < 2; ms++){
        #pragma unroll
        for (int nt = 0; nt < 8; nt++){
            int c0 = nh*64 + nt*8 + 2*tig;
            int kph = ast(c0 >> 1);
            int r0 = m0 + ms*16 + g;
            float2 fA = __half22float2(*(__half2*)&acc1h[ms][nt][0]);
            float y0 = silu_f(fA.x + b1s[c0]);
            float y1 = silu_f(fA.y + b1s[c0+1]);
            Ah[r0*ASTR + kph] = half_pack(y0, y1);
            float2 fB = __half22float2(*(__half2*)&acc1h[ms][nt][1]);
            float y2 = silu_f(fB.x + b1s[c0]);
            float y3 = silu_f(fB.y + b1s[c0+1]);
            Ah[(r0+8)*ASTR + kph] = half_pack(y2, y3);
        }
    }

    // ===== GEMM2: K=256, 4 chunks, fp32 accumulate =====
    float acc2[2][4][4];
    #pragma unroll
    for (int ms = 0; ms < 2; ms++)
        #pragma unroll
        for (int nt = 0; nt < 4; nt++)
            #pragma unroll
            for (int q = 0; q < 4; q++) acc2[ms][nt][q] = 0.f;

    {
        uint4 pf[2];
        #pragma unroll
        for (int q = 0; q < 2; q++){
            int r = t + q*512;
            pf[q] = *(const uint4*)&gW2h[(r>>3)*128 + (r&7)*4];
        }
        __syncthreads();                 // epilogue1 Ah writes done; last GEMM1 Bh reads done
        #pragma unroll
        for (int q = 0; q < 2; q++){
            int r = t + q*512;
            *(uint4*)&Bh[(r>>3)*BSTR + (r&7)*4] = pf[q];
        }
        __syncthreads();
        for (int c = 0; c < 4; c++){
            if (c + 1 < 4){
                #pragma unroll
                for (int q = 0; q < 2; q++){
                    int r = t + q*512;
                    pf[q] = *(const uint4*)&gW2h[(r>>3)*128 + (c+1)*32 + (r&7)*4];
                }
            }
            #pragma unroll
            for (int ksl = 0; ksl < 4; ksl++){
                int kp0 = c*32 + ksl*8;
                int kb  = ksl*8;
                unsigned ah[2][4];
                #pragma unroll
                for (int ms = 0; ms < 2; ms++){
                    int r0 = m0 + ms*16;
                    uint2 pa0 = *(const uint2*)&Ah[(r0+g  )*ASTR + kp0 + 2*tig];
                    uint2 pa1 = *(const uint2*)&Ah[(r0+g+8)*ASTR + kp0 + 2*tig];
                    ah[ms][0] = pa0.x; ah[ms][1] = pa1.x;
                    ah[ms][2] = pa0.y; ah[ms][3] = pa1.y;
                }
                #pragma unroll
                for (int nt = 0; nt < 4; nt++){
                    int n0 = nh*32 + nt*8;
                    uint2 pb = *(const uint2*)&Bh[(n0+g)*BSTR + kb + 2*tig];
                    mma16h(acc2[0][nt], ah[0], pb.x, pb.y);
                    mma16h(acc2[1][nt], ah[1], pb.x, pb.y);
                }
            }
            __syncthreads();
            if (c + 1 < 4){
                #pragma unroll
                for (int q = 0; q < 2; q++){
                    int r = t + q*512;
                    *(uint4*)&Bh[(r>>3)*BSTR + (r&7)*4] = pf[q];
                }
                __syncthreads();
            }
        }
    }

    // epilogue2: maskh *= silu(D2 + b2)  (cols nh*32..+31)
    #pragma unroll
    for (int ms = 0; ms < 2; ms++){
        #pragma unroll
        for (int nt = 0; nt < 4; nt++){
            int c0 = nh*32 + nt*8 + 2*tig;
            int e0 = m0 + ms*16 + g;
            size_t base0 = ((size_t)(bi0*64 + e0))*128 + c0;
            __half2* p0 = (__half2*)&g_maskh[base0];
            float2 mv = __half22float2(*p0);
            mv.x *= silu_f(acc2[ms][nt][0] + b2s[c0]);
            mv.y *= silu_f(acc2[ms][nt][1] + b2s[c0+1]);
            *p0 = __float22half2_rn(mv);
            __half2* p1 = (__half2*)&g_maskh[base0 + 8*128];
            float2 mw = __half22float2(*p1);
            mw.x *= silu_f(acc2[ms][nt][2] + b2s[c0]);
            mw.y *= silu_f(acc2[ms][nt][3] + b2s[c0+1]);
            *p1 = __float22half2_rn(mw);
        }
    }
}

// ---------------- K7: readout ----------------
__global__ void k_out(const int* __restrict__ z, const float* __restrict__ Wo,
                      const float* __restrict__ bo, float* __restrict__ out){
    int b = blockIdx.x, h = threadIdx.x;
    __shared__ float red[4];
    float acc = 0.f;
    for (int i = 0; i < NN; i++)
        if (z[b*NN + i] != 0) acc += g_s[(b*NN + i)*HH + h];
    float part = acc * Wo[h];
    float tot = blkred128(part, red);
    if (h == 0) out[b] = tot + bo[0];
}

// ---------------- launch ----------------
extern "C" void kernel_launch(void* const* d_in, const int* in_sizes, int n_in,
                              void* d_out, int out_size){
    const int*   z      = (const int*)  d_in[0];
    const float* pos    = (const float*)d_in[1];
    const float* emb_w  = (const float*)d_in[2];
    const float* emb2_w = (const float*)d_in[3];
    const float* Wef    = (const float*)d_in[4];
    const float* bef    = (const float*)d_in[5];
    const float* Ws2v   = (const float*)d_in[6];
    const float* bs2v   = (const float*)d_in[7];
    const float* Wq     = (const float*)d_in[8];
    const float* Wk     = (const float*)d_in[9];
    const float* Wd1    = (const float*)d_in[10];
    const float* bd1    = (const float*)d_in[11];
    const float* Wd2    = (const float*)d_in[12];
    const float* bd2    = (const float*)d_in[13];
    const float* Wint   = (const float*)d_in[14];
    const float* bint   = (const float*)d_in[15];
    const float* Wo     = (const float*)d_in[16];
    const float* bo     = (const float*)d_in[17];
    float* out = (float*)d_out;

    cudaFuncSetAttribute(k_dir, cudaFuncAttributeMaxDynamicSharedMemorySize, SMEM_DIR_BYTES);

    k_whalf<<<384, 128>>>(Wd1, Wd2);
    k_geom <<<BB*NN, 256>>>(z, pos, Wef, bef);
    k_embed<<<BB*NN, 128>>>(z, emb_w, emb2_w);
    k_gather<<<BB*NN/4, 256>>>(0);               // s += mask @ sn
    k_lin  <<<BB*NN/8, 128>>>(Ws2v, bs2v, 0);    // t = silu(LN(s@Ws2v+b))
    k_v    <<<BB*NN/4, 256>>>();
    k_vqk  <<<BB*NN*3/8, 128>>>(Wq, Wk);
    k_p    <<<BB*NN, 256>>>(Wd1);
    k_dir  <<<BB*NN/2, 512, SMEM_DIR_BYTES>>>(bd1, bd2);
    for (int l = 0; l < 3; l++){
        k_lin   <<<BB*NN/8, 128>>>(Wint + l*HH*HH, bint + l*HH, 1);  // sl
        k_gather<<<BB*NN/4, 256>>>(1);                                // s += mask @ sl
    }
    k_out<<<BB, 128>>>(z, Wo, bo, out);
}

// round 15
// speedup vs baseline: 1.0330x; 1.0330x over previous
#include <cuda_runtime.h>
#include <cuda_fp16.h>
#include <math.h>
#include <stdint.h>

#define BB 64
#define NN 64
#define HH 128
#define EFD 32
#define LN_EPS 1e-5f
#define CUT 10.0f
#define ASTR 136   // Ah row stride (words)
#define BSTR 40    // Bh row stride (words)

// ---------------- device scratch (no runtime allocation) ----------------
static __device__ __half g_maskh[BB*NN*NN*HH]; // 64 MB fp16 mask
static __device__ float g_ea  [BB*NN*NN];
static __device__ float g_ev  [BB*NN*NN*3];
static __device__ float g_s   [BB*NN*HH];
static __device__ float g_sn  [BB*NN*HH];
static __device__ float g_t   [BB*NN*HH];
static __device__ float g_v   [BB*NN*3*HH];
static __device__ float g_vq  [BB*NN*3*HH];
static __device__ float g_vk  [BB*NN*3*HH];
static __device__ float g_sl  [BB*NN*HH];
static __device__ float g_P   [BB*NN*3*256];   // P_i = V_i @ Wd1[0:128]
static __device__ unsigned gW1h3[256*64];      // Wd1 dir3 rows packed fp16 (x64), k-pair permuted
static __device__ unsigned gW2h [128*128];     // Wd2 packed fp16, k-pair permuted

// k-pair permutation within each 8-group: [0,4,1,5,2,6,3,7] -> pairs (t,t+4) adjacent
__device__ __forceinline__ int ast(int kp){
    return (kp & ~7) | (((kp & 3) << 1) | ((kp >> 2) & 1));
}

// ---- fast exp2 poly ----
__device__ __forceinline__ float exp2_poly(float f){
    float p = 1.3333558e-3f;
    p = fmaf(p, f, 9.6181291e-3f);
    p = fmaf(p, f, 5.5504109e-2f);
    p = fmaf(p, f, 2.4022651e-1f);
    p = fmaf(p, f, 6.9314718e-1f);
    p = fmaf(p, f, 1.0f);
    return p;
}
__device__ __forceinline__ float exp2n_f(float t){
    t = fmaxf(t, -126.0f);
    float fn = t + 12582912.0f;
    float n  = fn - 12582912.0f;
    float f  = t - n;
    int ni = __float_as_int(fn) - 0x4B400000;
    float scale = __int_as_float((ni + 127) << 23);
    return exp2_poly(f) * scale;
}
// silu: poly exp2 on FMA pipe + MUFU rcp (pipes overlap)
__device__ __forceinline__ float silu_f(float x){
    float t = x * (-1.442695041f);
    t = fminf(fmaxf(t, -126.0f), 126.0f);
    float fn = t + 12582912.0f;
    float n  = fn - 12582912.0f;
    float f  = t - n;
    int ni = __float_as_int(fn) - 0x4B400000;
    float scale = __int_as_float((ni + 127) << 23);
    float e = exp2_poly(f) * scale;   // e^{-x}
    float d = 1.0f + e;
    float y;
    asm("rcp.approx.f32 %0, %1;" : "=f"(y) : "f"(d));
    return x * y;
}

// ---- fp16 pack: {low16 = f16(f0), high16 = f16(f1)} ----
__device__ __forceinline__ unsigned half_pack(float f0, float f1){
    unsigned p;
    asm("cvt.rn.f16x2.f32 %0, %1, %2;" : "=r"(p) : "f"(f1), "f"(f0));
    return p;
}

// ---- mma.sync fp16 m16n8k16, fp32 accumulate ----
__device__ __forceinline__ void mma16h(float* c, const unsigned* a, unsigned b0, unsigned b1){
    asm("mma.sync.aligned.m16n8k16.row.col.f32.f16.f16.f32 "
        "{%0,%1,%2,%3},{%4,%5,%6,%7},{%8,%9},{%0,%1,%2,%3};"
        : "+f"(c[0]), "+f"(c[1]), "+f"(c[2]), "+f"(c[3])
        : "r"(a[0]), "r"(a[1]), "r"(a[2]), "r"(a[3]), "r"(b0), "r"(b1));
}

// block reduction for 128 threads (4 warps)
__device__ __forceinline__ float blkred128(float v, volatile float* red){
    #pragma unroll
    for (int o = 16; o > 0; o >>= 1) v += __shfl_xor_sync(0xffffffffu, v, o);
    if ((threadIdx.x & 31) == 0) red[threadIdx.x >> 5] = v;
    __syncthreads();
    v = red[0] + red[1] + red[2] + red[3];
    __syncthreads();
    return v;
}

// ---------------- K0: convert weights to packed fp16 (k-pair permuted) ----------------
__global__ void k_whalf(const float* __restrict__ Wd1, const float* __restrict__ Wd2){
    int n = blockIdx.x, kp = threadIdx.x;
    if (n < 256){
        if (kp < 64){
            float f0 = Wd1[(128 + 2*kp    )*256 + n] * 64.0f;
            float f1 = Wd1[(128 + 2*kp + 1)*256 + n] * 64.0f;
            gW1h3[n*64 + ast(kp)] = half_pack(f0, f1);
        }
    } else {
        int n2 = n - 256;
        float f0 = Wd2[(2*kp  )*128 + n2];
        float f1 = Wd2[(2*kp+1)*128 + n2];
        gW2h[n2*128 + ast(kp)] = half_pack(f0, f1);
    }
}

// ---------------- K1: geometry + RBF filter mask + embeddings (256 threads) ----------------
__global__ void k_geom(const int* __restrict__ z, const float* __restrict__ pos,
                       const float* __restrict__ Wef, const float* __restrict__ bef,
                       const float* __restrict__ emb_w, const float* __restrict__ emb2_w){
    int blk = blockIdx.x;
    int b = blk >> 6, i = blk & 63;
    int t = threadIdx.x;               // 256

    __shared__ float pos_s[NN][3];
    __shared__ int   z_s[NN];
    __shared__ float d_s[NN], ea_s[NN];
    __shared__ float ef_s[NN][EFD];
    __shared__ float Wef_s[EFD*HH];
    __shared__ float bef_s[HH];
    __shared__ float redA[4], redB[4];

    for (int r = t; r < EFD*HH; r += 256) Wef_s[r] = Wef[r];
    if (t < HH) bef_s[t] = bef[t];
    if (t < NN){
        z_s[t] = z[b*NN + t];
        pos_s[t][0] = pos[(b*NN + t)*3 + 0];
        pos_s[t][1] = pos[(b*NN + t)*3 + 1];
        pos_s[t][2] = pos[(b*NN + t)*3 + 2];
    }
    __syncthreads();

    if (t < NN){
        int j = t;
        float dx = pos_s[j][0] - pos_s[i][0];
        float dy = pos_s[j][1] - pos_s[i][1];
        float dz = pos_s[j][2] - pos_s[i][2];
        float d2 = dx*dx + dy*dy + dz*dz;
        float d  = sqrtf(fmaxf(d2, 1e-12f));
        d_s[j] = d;
        bool pair = (z_s[i] != 0) && (z_s[j] != 0) && (j != i);
        float ea = (pair && d < CUT) ? 0.5f*(cosf(3.14159265358979323846f * d / CUT) + 1.0f) : 0.0f;
        ea_s[j] = ea;
        g_ea[blk*NN + j] = ea;
        float inv = 1.0f / d;
        g_ev[(blk*NN + j)*3 + 0] = pair ? dx*inv : 0.0f;
        g_ev[(blk*NN + j)*3 + 1] = pair ? dy*inv : 0.0f;
        g_ev[(blk*NN + j)*3 + 2] = pair ? dz*inv : 0.0f;
    }
    __syncthreads();

    const float step = CUT / (float)(EFD - 1);
    for (int r = t; r < NN*EFD; r += 256){
        int j = r >> 5, k = r & 31;
        float dd = d_s[j] - step*(float)k;
        ef_s[j][k] = exp2n_f(-14.4269504089f * dd * dd);
    }
    __syncthreads();

    // ---- fused embed: s = emb[z_i]; sn = LN(emb2[z_i]) (threads < 128) ----
    {
        int zi = z_s[i];
        float sv = 0.f, x = 0.f;
        if (t < HH){
            sv = emb_w [zi*HH + t];
            x  = emb2_w[zi*HH + t];
        }
        float s1 = x, s2 = x*x;
        #pragma unroll
        for (int o = 16; o > 0; o >>= 1){
            s1 += __shfl_xor_sync(0xffffffffu, s1, o);
            s2 += __shfl_xor_sync(0xffffffffu, s2, o);
        }
        int wd = t >> 5, ln = t & 31;
        if (ln == 0 && wd < 4){ redA[wd] = s1; redB[wd] = s2; }
        __syncthreads();
        if (t < HH){
            float S1 = redA[0] + redA[1] + redA[2] + redA[3];
            float S2 = redB[0] + redB[1] + redB[2] + redB[3];
            float m = S1 * (1.0f/HH);
            float var = fmaxf(S2 * (1.0f/HH) - m*m, 0.0f);
            g_s [blk*HH + t] = sv;
            g_sn[blk*HH + t] = (x - m) * rsqrtf(var + LN_EPS);
        }
    }

    int hp = t & 63, jh = t >> 6;
    int h0 = 2*hp;
    __half2* mrow = (__half2*)(g_maskh + (size_t)blk*NN*HH);
    for (int jj = 0; jj < 16; jj++){
        int j = jh*16 + jj;
        float a0 = bef_s[h0], a1 = bef_s[h0+1];
        #pragma unroll
        for (int k = 0; k < EFD; k++){
            float e = ef_s[j][k];
            a0 = fmaf(e, Wef_s[k*HH + h0],     a0);
            a1 = fmaf(e, Wef_s[k*HH + h0 + 1], a1);
        }
        float ea = ea_s[j];
        float2 m; m.x = silu_f(a0) * ea; m.y = silu_f(a1) * ea;
        mrow[j*64 + hp] = __float22half2_rn(m);
    }
}

// ---------------- K2b / K6b: s += mask @ src (8 i-rows/block, half2 loads) ----------------
__global__ void k_gather(int sel){
    int blk = blockIdx.x;              // (b, i-group of 8)
    int b  = blk >> 3;
    int i0 = (blk & 7) * 8;
    int t  = threadIdx.x;              // 256
    int h2 = t & 63;
    int rg = t >> 6;                   // 0..3 -> rows rg*2, rg*2+1
    const float* src = sel ? g_sl : g_sn;
    __shared__ float srcs[NN*HH];
    const float* sb = src + b*NN*HH;
    for (int r = t; r < NN*HH; r += 256) srcs[r] = sb[r];
    __syncthreads();
    const __half2* m0 = (const __half2*)(g_maskh + (size_t)((b*NN + i0 + rg*2)*NN)*HH);
    float2 a0 = make_float2(0.f, 0.f), a1 = make_float2(0.f, 0.f);
    #pragma unroll 4
    for (int j = 0; j < NN; j++){
        float2 sv = *(const float2*)&srcs[j*HH + 2*h2];
        float2 q0 = __half22float2(m0[j*64 + h2]);
        float2 q1 = __half22float2(m0[4096 + j*64 + h2]);
        a0.x = fmaf(q0.x, sv.x, a0.x); a0.y = fmaf(q0.y, sv.y, a0.y);
        a1.x = fmaf(q1.x, sv.x, a1.x); a1.y = fmaf(q1.y, sv.y, a1.y);
    }
    int base = b*NN + i0 + rg*2;
    float2* sp0 = (float2*)&g_s[(base + 0)*HH + 2*h2];
    float2 s0 = *sp0; s0.x += a0.x; s0.y += a0.y; *sp0 = s0;
    float2* sp1 = (float2*)&g_s[(base + 1)*HH + 2*h2];
    float2 s1 = *sp1; s1.x += a1.x; s1.y += a1.y; *sp1 = s1;
}

// ---------------- K3 / K6a: dst = silu(LN(s @ W + bias)), 8 atoms per block ----------------
__global__ void k_lin(const float* __restrict__ W, const float* __restrict__ bias,
                      int dst_sel){
    int blk = blockIdx.x;
    int h = threadIdx.x;               // 128
    __shared__ float xs[8][HH];
    __shared__ float ys[8][HH];
    __shared__ float mm[8], rr[8];
    for (int r = h; r < 8*HH; r += 128) ((float*)xs)[r] = g_s[blk*8*HH + r];
    __syncthreads();
    float bh = bias[h];
    float acc[8];
    #pragma unroll
    for (int a = 0; a < 8; a++) acc[a] = bh;
    #pragma unroll 4
    for (int k = 0; k < HH; k++){
        float w = W[k*HH + h];
        #pragma unroll
        for (int a = 0; a < 8; a++) acc[a] = fmaf(xs[a][k], w, acc[a]);
    }
    #pragma unroll
    for (int a = 0; a < 8; a++) ys[a][h] = acc[a];
    __syncthreads();
    {
        int w = h >> 5, l = h & 31;
        #pragma unroll
        for (int aa = 0; aa < 2; aa++){
            int a = w + aa*4;
            float s1 = 0.f, s2 = 0.f;
            #pragma unroll
            for (int c = l; c < HH; c += 32){ float v = ys[a][c]; s1 += v; s2 += v*v; }
            #pragma unroll
            for (int o = 16; o > 0; o >>= 1){
                s1 += __shfl_xor_sync(0xffffffffu, s1, o);
                s2 += __shfl_xor_sync(0xffffffffu, s2, o);
            }
            if (l == 0){
                float m = s1 * (1.0f/HH);
                float var = fmaxf(s2 * (1.0f/HH) - m*m, 0.0f);
                mm[a] = m; rr[a] = rsqrtf(var + LN_EPS);
            }
        }
    }
    __syncthreads();
    float* dst = dst_sel ? g_sl : g_t;
    #pragma unroll
    for (int a = 0; a < 8; a++)
        dst[(blk*8 + a)*HH + h] = silu_f((ys[a][h] - mm[a]) * rr[a]);
}

// ---------------- K4a: v = sum_j mask*t*ev (4 i-rows/block, half2 loads) ----------------
__global__ void k_v(){
    int blk = blockIdx.x;
    int b  = blk >> 4;
    int i0 = (blk & 15) * 4;
    int t  = threadIdx.x;              // 256
    int h2 = t & 63;
    int rg = t >> 6;
    __shared__ float ts[NN*HH];
    __shared__ float evl[4][NN*3];
    const float* tb = g_t + b*NN*HH;
    for (int r = t; r < NN*HH; r += 256) ts[r] = tb[r];
    for (int r = t; r < 4*NN*3; r += 256) ((float*)evl)[r] = g_ev[(b*NN + i0)*NN*3 + r];
    __syncthreads();
    const __half2* m0 = (const __half2*)(g_maskh + (size_t)((b*NN + i0 + rg)*NN)*HH);
    float a00 = 0.f, a01 = 0.f, a10 = 0.f, a11 = 0.f, a20 = 0.f, a21 = 0.f;
    #pragma unroll 4
    for (int j = 0; j < NN; j++){
        float2 tv = *(const float2*)&ts[j*HH + 2*h2];
        float2 mq = __half22float2(m0[j*64 + h2]);
        float m0v = mq.x * tv.x, m1v = mq.y * tv.y;
        float e0 = evl[rg][j*3+0], e1 = evl[rg][j*3+1], e2 = evl[rg][j*3+2];
        a00 = fmaf(m0v, e0, a00); a01 = fmaf(m1v, e0, a01);
        a10 = fmaf(m0v, e1, a10); a11 = fmaf(m1v, e1, a11);
        a20 = fmaf(m0v, e2, a20); a21 = fmaf(m1v, e2, a21);
    }
    int base = (b*NN + i0 + rg)*3;
    *(float2*)&g_v[(base + 0)*HH + 2*h2] = make_float2(a00, a01);
    *(float2*)&g_v[(base + 1)*HH + 2*h2] = make_float2(a10, a11);
    *(float2*)&g_v[(base + 2)*HH + 2*h2] = make_float2(a20, a21);
}

// ---------------- K4b: fused vq/vk + P (one block per atom, 256 threads) ----------------
__global__ void k_vp(const float* __restrict__ Wq, const float* __restrict__ Wk,
                     const float* __restrict__ Wd1){
    int bi = blockIdx.x, t = threadIdx.x;
    __shared__ float vs[3*HH];
    for (int r = t; r < 3*HH; r += 256) vs[r] = g_v[bi*3*HH + r];
    __syncthreads();
    // phase A: vq (t<128) / vk (t>=128), 3 rows each
    {
        int h = t & 127;
        const float* W = (t < 128) ? Wq : Wk;
        float a0 = 0.f, a1 = 0.f, a2 = 0.f;
        #pragma unroll 4
        for (int k = 0; k < HH; k++){
            float w = W[k*HH + h];
            a0 = fmaf(vs[k],        w, a0);
            a1 = fmaf(vs[HH + k],   w, a1);
            a2 = fmaf(vs[2*HH + k], w, a2);
        }
        float* dst = (t < 128) ? g_vq : g_vk;
        dst[bi*3*HH + h]        = a0;
        dst[bi*3*HH + HH + h]   = a1;
        dst[bi*3*HH + 2*HH + h] = a2;
    }
    // phase B: P = V @ Wd1[0:128] (3 x 256)
    {
        int n = t;
        float p0 = 0.f, p1 = 0.f, p2 = 0.f;
        #pragma unroll 4
        for (int k = 0; k < HH; k++){
            float w = Wd1[k*256 + n];
            p0 = fmaf(vs[k],        w, p0);
            p1 = fmaf(vs[HH + k],   w, p1);
            p2 = fmaf(vs[2*HH + k], w, p2);
        }
        g_P[bi*768 + n]       = p0;
        g_P[bi*768 + 256 + n] = p1;
        g_P[bi*768 + 512 + n] = p2;
    }
}

// ---------------- K5: directional MLP (512 threads, LDS.64 fragment loads) ----------------
// smem words: Ah 128*136=17408 | Bh 256*40=10240 | b1s 256 | b2s 128 = 28032 (112128 B)
#define SMEM_DIR_BYTES (28032*4)
__global__ void __launch_bounds__(512) k_dir(const float* __restrict__ bd1,
                                             const float* __restrict__ bd2){
    extern __shared__ unsigned smu[];
    unsigned* Ah = smu;                          // [e][kp], stride ASTR, k-pair permuted
    unsigned* Bh = smu + 17408;                  // staging [n][kp'], stride BSTR, permuted
    float* b1s = (float*)(smu + 27648);
    float* b2s = (float*)(smu + 27904);
    // pre-GEMM scratch overlaps Bh (dead before first staging store)
    float* eas = (float*)(Bh);                   // 128
    float* evs = (float*)(Bh + 128);             // 384
    float* vks = (float*)(Bh + 512);             // 768
    float* Ps  = (float*)(Bh + 1280);            // 1536

    int t = threadIdx.x, lane = t & 31, wid = t >> 5;
    int g = lane >> 2, tig = lane & 3;
    int bi0 = blockIdx.x * 2, bbase = bi0 & ~63;

    if (t < 256) b1s[t] = bd1[t];
    if (t < 128) b2s[t] = bd2[t];
    if (t < 128) eas[t] = g_ea[bi0*64 + t];
    for (int r = t; r < 384;  r += 512) evs[r] = g_ev[bi0*192 + r];
    for (int r = t; r < 768;  r += 512) vks[r] = g_vk[bi0*384 + r];
    for (int r = t; r < 1536; r += 512) Ps [r] = g_P [bi0*768 + r];
    __syncthreads();

    // build dir3 (scaled 1/64) -> Ah kp 0..63 (permuted positions)
    {
        int kp3 = t & 63, grp = t >> 6;          // grp 0..7
        int i  = grp & 1, jq = grp >> 1;         // jq 0..3: 16 j each
        int kk = 2*kp3;
        int astk = ast(kp3);
        float u0 = vks[i*384 + kk],     u1 = vks[i*384 + 128 + kk], u2 = vks[i*384 + 256 + kk];
        float w0 = vks[i*384 + kk + 1], w1 = vks[i*384 + 129 + kk], w2 = vks[i*384 + 257 + kk];
        for (int jj = 0; jj < 16; jj++){
            int j = jq*16 + jj;
            int e = i*64 + j;
            float ea = eas[e] * 0.015625f;
            const float* vq = g_vq + (bbase + j)*384 + kk;
            float2 q0 = *(const float2*)vq;
            float2 q1 = *(const float2*)(vq + 128);
            float2 q2 = *(const float2*)(vq + 256);
            float f0 = (q0.x*u0 + q1.x*u1 + q2.x*u2) * ea;
            float f1 = (q0.y*w0 + q1.y*w1 + q2.y*w2) * ea;
            Ah[e*ASTR + astk] = half_pack(f0, f1);
        }
    }

    int m0 = (wid & 3) * 32;                     // 4 m-groups x 32 rows
    int nh = wid >> 2;                           // 4 n-groups

    // init acc1 with dir2 low-rank contribution (GEMM1 cols nh*64 .. +63)
    float acc1[2][8][4];
    #pragma unroll
    for (int ms = 0; ms < 2; ms++){
        int ea_r = m0 + ms*16 + g;
        int eb_r = ea_r + 8;
        int ia = ea_r >> 6, ib = eb_r >> 6;
        float ca0 = evs[ea_r*3], ca1 = evs[ea_r*3+1], ca2 = evs[ea_r*3+2];
        float cb0 = evs[eb_r*3], cb1 = evs[eb_r*3+1], cb2 = evs[eb_r*3+2];
        float wa = eas[ea_r], wb = eas[eb_r];
        const float* Pa = Ps + ia*768;
        const float* Pb = Ps + ib*768;
        #pragma unroll
        for (int nt = 0; nt < 8; nt++){
            int c0 = nh*64 + nt*8 + 2*tig;
            acc1[ms][nt][0] = wa * (ca0*Pa[c0]   + ca1*Pa[256+c0]   + ca2*Pa[512+c0]);
            acc1[ms][nt][1] = wa * (ca0*Pa[c0+1] + ca1*Pa[256+c0+1] + ca2*Pa[512+c0+1]);
            acc1[ms][nt][2] = wb * (cb0*Pb[c0]   + cb1*Pb[256+c0]   + cb2*Pb[512+c0]);
            acc1[ms][nt][3] = wb * (cb0*Pb[c0+1] + cb1*Pb[256+c0+1] + cb2*Pb[512+c0+1]);
        }
    }

    // ===== GEMM1 (dir3 half): K=128, 2 chunks, single buffer + reg prefetch =====
    {
        uint4 pf[4];
        #pragma unroll
        for (int q = 0; q < 4; q++){
            int r = t + q*512;
            pf[q] = *(const uint4*)&gW1h3[(r>>3)*64 + (r&7)*4];
        }
        __syncthreads();                 // scratch reads (build + init acc1) done
        #pragma unroll
        for (int q = 0; q < 4; q++){
            int r = t + q*512;
            *(uint4*)&Bh[(r>>3)*BSTR + (r&7)*4] = pf[q];
        }
        __syncthreads();
        for (int c = 0; c < 2; c++){
            if (c == 0){
                #pragma unroll
                for (int q = 0; q < 4; q++){
                    int r = t + q*512;
                    pf[q] = *(const uint4*)&gW1h3[(r>>3)*64 + 32 + (r&7)*4];
                }
            }
            #pragma unroll
            for (int ksl = 0; ksl < 4; ksl++){
                int kp0 = c*32 + ksl*8;
                int kb  = ksl*8;
                unsigned ah[2][4];
                #pragma unroll
                for (int ms = 0; ms < 2; ms++){
                    int r0 = m0 + ms*16;
                    uint2 pa0 = *(const uint2*)&Ah[(r0+g  )*ASTR + kp0 + 2*tig];
                    uint2 pa1 = *(const uint2*)&Ah[(r0+g+8)*ASTR + kp0 + 2*tig];
                    ah[ms][0] = pa0.x; ah[ms][1] = pa1.x;
                    ah[ms][2] = pa0.y; ah[ms][3] = pa1.y;
                }
                #pragma unroll
                for (int nt = 0; nt < 8; nt++){
                    int n0 = nh*64 + nt*8;
                    uint2 pb = *(const uint2*)&Bh[(n0+g)*BSTR + kb + 2*tig];
                    mma16h(acc1[0][nt], ah[0], pb.x, pb.y);
                    mma16h(acc1[1][nt], ah[1], pb.x, pb.y);
                }
            }
            __syncthreads();
            if (c == 0){
                #pragma unroll
                for (int q = 0; q < 4; q++){
                    int r = t + q*512;
                    *(uint4*)&Bh[(r>>3)*BSTR + (r&7)*4] = pf[q];
                }
                __syncthreads();
            }
        }
    }

    // epilogue1: h1 = silu(D1 + b1) packed back into Ah (permuted positions)
    #pragma unroll
    for (int ms = 0; ms < 2; ms++){
        #pragma unroll
        for (int nt = 0; nt < 8; nt++){
            int c0 = nh*64 + nt*8 + 2*tig;
            int kph = ast(c0 >> 1);
            int r0 = m0 + ms*16 + g;
            float y0 = silu_f(acc1[ms][nt][0] + b1s[c0]);
            float y1 = silu_f(acc1[ms][nt][1] + b1s[c0+1]);
            Ah[r0*ASTR + kph] = half_pack(y0, y1);
            float y2 = silu_f(acc1[ms][nt][2] + b1s[c0]);
            float y3 = silu_f(acc1[ms][nt][3] + b1s[c0+1]);
            Ah[(r0+8)*ASTR + kph] = half_pack(y2, y3);
        }
    }

    // ===== GEMM2: K=256, 4 chunks, single buffer + reg prefetch =====
    float acc2[2][4][4];
    #pragma unroll
    for (int ms = 0; ms < 2; ms++)
        #pragma unroll
        for (int nt = 0; nt < 4; nt++)
            #pragma unroll
            for (int q = 0; q < 4; q++) acc2[ms][nt][q] = 0.f;

    {
        uint4 pf[2];
        #pragma unroll
        for (int q = 0; q < 2; q++){
            int r = t + q*512;
            pf[q] = *(const uint4*)&gW2h[(r>>3)*128 + (r&7)*4];
        }
        __syncthreads();                 // epilogue1 Ah writes done; last GEMM1 Bh reads done
        #pragma unroll
        for (int q = 0; q < 2; q++){
            int r = t + q*512;
            *(uint4*)&Bh[(r>>3)*BSTR + (r&7)*4] = pf[q];
        }
        __syncthreads();
        for (int c = 0; c < 4; c++){
            if (c + 1 < 4){
                #pragma unroll
                for (int q = 0; q < 2; q++){
                    int r = t + q*512;
                    pf[q] = *(const uint4*)&gW2h[(r>>3)*128 + (c+1)*32 + (r&7)*4];
                }
            }
            #pragma unroll
            for (int ksl = 0; ksl < 4; ksl++){
                int kp0 = c*32 + ksl*8;
                int kb  = ksl*8;
                unsigned ah[2][4];
                #pragma unroll
                for (int ms = 0; ms < 2; ms++){
                    int r0 = m0 + ms*16;
                    uint2 pa0 = *(const uint2*)&Ah[(r0+g  )*ASTR + kp0 + 2*tig];
                    uint2 pa1 = *(const uint2*)&Ah[(r0+g+8)*ASTR + kp0 + 2*tig];
                    ah[ms][0] = pa0.x; ah[ms][1] = pa1.x;
                    ah[ms][2] = pa0.y; ah[ms][3] = pa1.y;
                }
                #pragma unroll
                for (int nt = 0; nt < 4; nt++){
                    int n0 = nh*32 + nt*8;
                    uint2 pb = *(const uint2*)&Bh[(n0+g)*BSTR + kb + 2*tig];
                    mma16h(acc2[0][nt], ah[0], pb.x, pb.y);
                    mma16h(acc2[1][nt], ah[1], pb.x, pb.y);
                }
            }
            __syncthreads();
            if (c + 1 < 4){
                #pragma unroll
                for (int q = 0; q < 2; q++){
                    int r = t + q*512;
                    *(uint4*)&Bh[(r>>3)*BSTR + (r&7)*4] = pf[q];
                }
                __syncthreads();
            }
        }
    }

    // epilogue2: maskh *= silu(D2 + b2)  (cols nh*32..+31)
    #pragma unroll
    for (int ms = 0; ms < 2; ms++){
        #pragma unroll
        for (int nt = 0; nt < 4; nt++){
            int c0 = nh*32 + nt*8 + 2*tig;
            int e0 = m0 + ms*16 + g;
            size_t base0 = ((size_t)(bi0*64 + e0))*128 + c0;
            __half2* p0 = (__half2*)&g_maskh[base0];
            float2 mv = __half22float2(*p0);
            mv.x *= silu_f(acc2[ms][nt][0] + b2s[c0]);
            mv.y *= silu_f(acc2[ms][nt][1] + b2s[c0+1]);
            *p0 = __float22half2_rn(mv);
            __half2* p1 = (__half2*)&g_maskh[base0 + 8*128];
            float2 mw = __half22float2(*p1);
            mw.x *= silu_f(acc2[ms][nt][2] + b2s[c0]);
            mw.y *= silu_f(acc2[ms][nt][3] + b2s[c0+1]);
            *p1 = __float22half2_rn(mw);
        }
    }
}

// ---------------- K7: readout ----------------
__global__ void k_out(const int* __restrict__ z, const float* __restrict__ Wo,
                      const float* __restrict__ bo, float* __restrict__ out){
    int b = blockIdx.x, h = threadIdx.x;
    __shared__ float red[4];
    float acc = 0.f;
    for (int i = 0; i < NN; i++)
        if (z[b*NN + i] != 0) acc += g_s[(b*NN + i)*HH + h];
    float part = acc * Wo[h];
    float tot = blkred128(part, red);
    if (h == 0) out[b] = tot + bo[0];
}

// ---------------- launch ----------------
extern "C" void kernel_launch(void* const* d_in, const int* in_sizes, int n_in,
                              void* d_out, int out_size){
    const int*   z      = (const int*)  d_in[0];
    const float* pos    = (const float*)d_in[1];
    const float* emb_w  = (const float*)d_in[2];
    const float* emb2_w = (const float*)d_in[3];
    const float* Wef    = (const float*)d_in[4];
    const float* bef    = (const float*)d_in[5];
    const float* Ws2v   = (const float*)d_in[6];
    const float* bs2v   = (const float*)d_in[7];
    const float* Wq     = (const float*)d_in[8];
    const float* Wk     = (const float*)d_in[9];
    const float* Wd1    = (const float*)d_in[10];
    const float* bd1    = (const float*)d_in[11];
    const float* Wd2    = (const float*)d_in[12];
    const float* bd2    = (const float*)d_in[13];
    const float* Wint   = (const float*)d_in[14];
    const float* bint   = (const float*)d_in[15];
    const float* Wo     = (const float*)d_in[16];
    const float* bo     = (const float*)d_in[17];
    float* out = (float*)d_out;

    cudaFuncSetAttribute(k_dir, cudaFuncAttributeMaxDynamicSharedMemorySize, SMEM_DIR_BYTES);

    k_whalf<<<384, 128>>>(Wd1, Wd2);
    k_geom <<<BB*NN, 256>>>(z, pos, Wef, bef, emb_w, emb2_w);
    k_gather<<<BB*NN/8, 256>>>(0);               // s += mask @ sn
    k_lin  <<<BB*NN/8, 128>>>(Ws2v, bs2v, 0);    // t = silu(LN(s@Ws2v+b))
    k_v    <<<BB*NN/4, 256>>>();
    k_vp   <<<BB*NN, 256>>>(Wq, Wk, Wd1);
    k_dir  <<<BB*NN/2, 512, SMEM_DIR_BYTES>>>(bd1, bd2);
    for (int l = 0; l < 3; l++){
        k_lin   <<<BB*NN/8, 128>>>(Wint + l*HH*HH, bint + l*HH, 1);  // sl
        k_gather<<<BB*NN/8, 256>>>(1);                                // s += mask @ sl
    }
    k_out<<<BB, 128>>>(z, Wo, bo, out);
}

// round 16
// speedup vs baseline: 1.0579x; 1.0242x over previous
#include <cuda_runtime.h>
#include <cuda_fp16.h>
#include <math.h>
#include <stdint.h>

#define BB 64
#define NN 64
#define HH 128
#define EFD 32
#define LN_EPS 1e-5f
#define CUT 10.0f
#define ASTR 136   // Ah row stride (words)
#define BSTR 40    // Bh row stride (words)

// ---------------- device scratch (no runtime allocation) ----------------
static __device__ __half g_maskh[BB*NN*NN*HH]; // 64 MB fp16 mask
static __device__ float g_ea  [BB*NN*NN];
static __device__ float g_ev  [BB*NN*NN*3];
static __device__ float g_s   [BB*NN*HH];
static __device__ float g_sn  [BB*NN*HH];
static __device__ float g_t   [BB*NN*HH];
static __device__ float g_v   [BB*NN*3*HH];
static __device__ float g_vq  [BB*NN*3*HH];
static __device__ float g_vk  [BB*NN*3*HH];
static __device__ float g_sl  [BB*NN*HH];
static __device__ float g_P   [BB*NN*3*256];   // P_i = V_i @ Wd1[0:128]
static __device__ unsigned gW1h3[256*64];      // Wd1 dir3 rows packed fp16 (x64), k-pair permuted
static __device__ unsigned gW2h [128*128];     // Wd2 packed fp16, k-pair permuted

// k-pair permutation within each 8-group: [0,4,1,5,2,6,3,7] -> pairs (t,t+4) adjacent
__device__ __forceinline__ int ast(int kp){
    return (kp & ~7) | (((kp & 3) << 1) | ((kp >> 2) & 1));
}

// ---- fast exp2 poly ----
__device__ __forceinline__ float exp2_poly(float f){
    float p = 1.3333558e-3f;
    p = fmaf(p, f, 9.6181291e-3f);
    p = fmaf(p, f, 5.5504109e-2f);
    p = fmaf(p, f, 2.4022651e-1f);
    p = fmaf(p, f, 6.9314718e-1f);
    p = fmaf(p, f, 1.0f);
    return p;
}
__device__ __forceinline__ float exp2n_f(float t){
    t = fmaxf(t, -126.0f);
    float fn = t + 12582912.0f;
    float n  = fn - 12582912.0f;
    float f  = t - n;
    int ni = __float_as_int(fn) - 0x4B400000;
    float scale = __int_as_float((ni + 127) << 23);
    return exp2_poly(f) * scale;
}
// silu: poly exp2 on FMA pipe + MUFU rcp (pipes overlap)
__device__ __forceinline__ float silu_f(float x){
    float t = x * (-1.442695041f);
    t = fminf(fmaxf(t, -126.0f), 126.0f);
    float fn = t + 12582912.0f;
    float n  = fn - 12582912.0f;
    float f  = t - n;
    int ni = __float_as_int(fn) - 0x4B400000;
    float scale = __int_as_float((ni + 127) << 23);
    float e = exp2_poly(f) * scale;   // e^{-x}
    float d = 1.0f + e;
    float y;
    asm("rcp.approx.f32 %0, %1;" : "=f"(y) : "f"(d));
    return x * y;
}

// ---- fp16 pack: {low16 = f16(f0), high16 = f16(f1)} ----
__device__ __forceinline__ unsigned half_pack(float f0, float f1){
    unsigned p;
    asm("cvt.rn.f16x2.f32 %0, %1, %2;" : "=r"(p) : "f"(f1), "f"(f0));
    return p;
}

// ---- mma.sync fp16 m16n8k16, fp32 accumulate ----
__device__ __forceinline__ void mma16h(float* c, const unsigned* a, unsigned b0, unsigned b1){
    asm("mma.sync.aligned.m16n8k16.row.col.f32.f16.f16.f32 "
        "{%0,%1,%2,%3},{%4,%5,%6,%7},{%8,%9},{%0,%1,%2,%3};"
        : "+f"(c[0]), "+f"(c[1]), "+f"(c[2]), "+f"(c[3])
        : "r"(a[0]), "r"(a[1]), "r"(a[2]), "r"(a[3]), "r"(b0), "r"(b1));
}

// block reduction for 128 threads (4 warps)
__device__ __forceinline__ float blkred128(float v, volatile float* red){
    #pragma unroll
    for (int o = 16; o > 0; o >>= 1) v += __shfl_xor_sync(0xffffffffu, v, o);
    if ((threadIdx.x & 31) == 0) red[threadIdx.x >> 5] = v;
    __syncthreads();
    v = red[0] + red[1] + red[2] + red[3];
    __syncthreads();
    return v;
}

// ---------------- K0: convert weights to packed fp16 (k-pair permuted) ----------------
__global__ void k_whalf(const float* __restrict__ Wd1, const float* __restrict__ Wd2){
    int n = blockIdx.x, kp = threadIdx.x;
    if (n < 256){
        if (kp < 64){
            float f0 = Wd1[(128 + 2*kp    )*256 + n] * 64.0f;
            float f1 = Wd1[(128 + 2*kp + 1)*256 + n] * 64.0f;
            gW1h3[n*64 + ast(kp)] = half_pack(f0, f1);
        }
    } else {
        int n2 = n - 256;
        float f0 = Wd2[(2*kp  )*128 + n2];
        float f1 = Wd2[(2*kp+1)*128 + n2];
        gW2h[n2*128 + ast(kp)] = half_pack(f0, f1);
    }
}

// ---------------- K0b: P_i = V_i @ Wd1[0:128]  (3 x 256 per atom, fp32) ----------------
__global__ void k_p(const float* __restrict__ Wd1){
    int bi = blockIdx.x, n = threadIdx.x;
    __shared__ float vs[3*HH];
    for (int r = n; r < 3*HH; r += 256) vs[r] = g_v[bi*3*HH + r];
    __syncthreads();
    float p0 = 0.f, p1 = 0.f, p2 = 0.f;
    #pragma unroll 4
    for (int k = 0; k < HH; k++){
        float w = Wd1[k*256 + n];
        p0 = fmaf(vs[k],        w, p0);
        p1 = fmaf(vs[HH + k],   w, p1);
        p2 = fmaf(vs[2*HH + k], w, p2);
    }
    g_P[bi*768 + n]       = p0;
    g_P[bi*768 + 256 + n] = p1;
    g_P[bi*768 + 512 + n] = p2;
}

// ---------------- K1: geometry + RBF filter mask (256 threads) ----------------
__global__ void k_geom(const int* __restrict__ z, const float* __restrict__ pos,
                       const float* __restrict__ Wef, const float* __restrict__ bef){
    int blk = blockIdx.x;
    int b = blk >> 6, i = blk & 63;
    int t = threadIdx.x;               // 256

    __shared__ float pos_s[NN][3];
    __shared__ int   z_s[NN];
    __shared__ float d_s[NN], ea_s[NN];
    __shared__ float ef_s[NN][EFD];
    __shared__ float Wef_s[EFD*HH];
    __shared__ float bef_s[HH];

    for (int r = t; r < EFD*HH; r += 256) Wef_s[r] = Wef[r];
    if (t < HH) bef_s[t] = bef[t];
    if (t < NN){
        z_s[t] = z[b*NN + t];
        pos_s[t][0] = pos[(b*NN + t)*3 + 0];
        pos_s[t][1] = pos[(b*NN + t)*3 + 1];
        pos_s[t][2] = pos[(b*NN + t)*3 + 2];
    }
    __syncthreads();

    if (t < NN){
        int j = t;
        float dx = pos_s[j][0] - pos_s[i][0];
        float dy = pos_s[j][1] - pos_s[i][1];
        float dz = pos_s[j][2] - pos_s[i][2];
        float d2 = dx*dx + dy*dy + dz*dz;
        float d  = sqrtf(fmaxf(d2, 1e-12f));
        d_s[j] = d;
        bool pair = (z_s[i] != 0) && (z_s[j] != 0) && (j != i);
        float ea = (pair && d < CUT) ? 0.5f*(cosf(3.14159265358979323846f * d / CUT) + 1.0f) : 0.0f;
        ea_s[j] = ea;
        g_ea[blk*NN + j] = ea;
        float inv = 1.0f / d;
        g_ev[(blk*NN + j)*3 + 0] = pair ? dx*inv : 0.0f;
        g_ev[(blk*NN + j)*3 + 1] = pair ? dy*inv : 0.0f;
        g_ev[(blk*NN + j)*3 + 2] = pair ? dz*inv : 0.0f;
    }
    __syncthreads();

    const float step = CUT / (float)(EFD - 1);
    for (int r = t; r < NN*EFD; r += 256){
        int j = r >> 5, k = r & 31;
        float dd = d_s[j] - step*(float)k;
        ef_s[j][k] = exp2n_f(-14.4269504089f * dd * dd);
    }
    __syncthreads();

    int hp = t & 63, jh = t >> 6;
    int h0 = 2*hp;
    __half2* mrow = (__half2*)(g_maskh + (size_t)blk*NN*HH);
    for (int jj = 0; jj < 16; jj++){
        int j = jh*16 + jj;
        float a0 = bef_s[h0], a1 = bef_s[h0+1];
        #pragma unroll
        for (int k = 0; k < EFD; k++){
            float e = ef_s[j][k];
            a0 = fmaf(e, Wef_s[k*HH + h0],     a0);
            a1 = fmaf(e, Wef_s[k*HH + h0 + 1], a1);
        }
        float ea = ea_s[j];
        float2 m; m.x = silu_f(a0) * ea; m.y = silu_f(a1) * ea;
        mrow[j*64 + hp] = __float22half2_rn(m);
    }
}

// ---------------- K2a: s = emb[z];  sn = LN(emb2[z]) ----------------
__global__ void k_embed(const int* __restrict__ z, const float* __restrict__ emb_w,
                        const float* __restrict__ emb2_w){
    int a = blockIdx.x, h = threadIdx.x;
    __shared__ float red[4];
    int zi = z[a];
    g_s[a*HH + h] = emb_w[zi*HH + h];
    float x = emb2_w[zi*HH + h];
    float s1 = blkred128(x, red);
    float s2 = blkred128(x*x, red);
    float m = s1 * (1.0f/HH);
    float var = fmaxf(s2 * (1.0f/HH) - m*m, 0.0f);
    g_sn[a*HH + h] = (x - m) * rsqrtf(var + LN_EPS);
}

// ---------------- K2b / K6b: s += mask @ src (8 i-rows/block, half2 loads) ----------------
__global__ void k_gather(int sel){
    int blk = blockIdx.x;              // (b, i-group of 8)
    int b  = blk >> 3;
    int i0 = (blk & 7) * 8;
    int t  = threadIdx.x;              // 256
    int h2 = t & 63;
    int rg = t >> 6;                   // 0..3 -> rows rg*2, rg*2+1
    const float* src = sel ? g_sl : g_sn;
    __shared__ float srcs[NN*HH];
    const float* sb = src + b*NN*HH;
    for (int r = t; r < NN*HH; r += 256) srcs[r] = sb[r];
    __syncthreads();
    const __half2* m0 = (const __half2*)(g_maskh + (size_t)((b*NN + i0 + rg*2)*NN)*HH);
    float2 a0 = make_float2(0.f, 0.f), a1 = make_float2(0.f, 0.f);
    #pragma unroll 4
    for (int j = 0; j < NN; j++){
        float2 sv = *(const float2*)&srcs[j*HH + 2*h2];
        float2 q0 = __half22float2(m0[j*64 + h2]);
        float2 q1 = __half22float2(m0[4096 + j*64 + h2]);
        a0.x = fmaf(q0.x, sv.x, a0.x); a0.y = fmaf(q0.y, sv.y, a0.y);
        a1.x = fmaf(q1.x, sv.x, a1.x); a1.y = fmaf(q1.y, sv.y, a1.y);
    }
    int base = b*NN + i0 + rg*2;
    float2* sp0 = (float2*)&g_s[(base + 0)*HH + 2*h2];
    float2 s0 = *sp0; s0.x += a0.x; s0.y += a0.y; *sp0 = s0;
    float2* sp1 = (float2*)&g_s[(base + 1)*HH + 2*h2];
    float2 s1 = *sp1; s1.x += a1.x; s1.y += a1.y; *sp1 = s1;
}

// ---------------- K3 / K6a: dst = silu(LN(s @ W + bias)), 4 atoms per block ----------------
__global__ void k_lin(const float* __restrict__ W, const float* __restrict__ bias,
                      int dst_sel){
    int blk = blockIdx.x;
    int h = threadIdx.x;               // 128
    __shared__ float xs[4][HH];
    __shared__ float ys[4][HH];
    __shared__ float mm[4], rr[4];
    for (int r = h; r < 4*HH; r += 128) ((float*)xs)[r] = g_s[blk*4*HH + r];
    __syncthreads();
    float bh = bias[h];
    float a0 = bh, a1 = bh, a2 = bh, a3 = bh;
    #pragma unroll 8
    for (int k = 0; k < HH; k++){
        float w = W[k*HH + h];
        a0 = fmaf(xs[0][k], w, a0);
        a1 = fmaf(xs[1][k], w, a1);
        a2 = fmaf(xs[2][k], w, a2);
        a3 = fmaf(xs[3][k], w, a3);
    }
    ys[0][h] = a0; ys[1][h] = a1; ys[2][h] = a2; ys[3][h] = a3;
    __syncthreads();
    {
        int w = h >> 5, l = h & 31;
        float s1 = 0.f, s2 = 0.f;
        #pragma unroll
        for (int c = l; c < HH; c += 32){ float v = ys[w][c]; s1 += v; s2 += v*v; }
        #pragma unroll
        for (int o = 16; o > 0; o >>= 1){
            s1 += __shfl_xor_sync(0xffffffffu, s1, o);
            s2 += __shfl_xor_sync(0xffffffffu, s2, o);
        }
        if (l == 0){
            float m = s1 * (1.0f/HH);
            float var = fmaxf(s2 * (1.0f/HH) - m*m, 0.0f);
            mm[w] = m; rr[w] = rsqrtf(var + LN_EPS);
        }
    }
    __syncthreads();
    float* dst = dst_sel ? g_sl : g_t;
    #pragma unroll
    for (int a = 0; a < 4; a++)
        dst[(blk*4 + a)*HH + h] = silu_f((ys[a][h] - mm[a]) * rr[a]);
}

// ---------------- K4a: v = sum_j mask*t*ev (4 i-rows/block, half2 loads) ----------------
__global__ void k_v(){
    int blk = blockIdx.x;
    int b  = blk >> 4;
    int i0 = (blk & 15) * 4;
    int t  = threadIdx.x;              // 256
    int h2 = t & 63;
    int rg = t >> 6;
    __shared__ float ts[NN*HH];
    __shared__ float evl[4][NN*3];
    const float* tb = g_t + b*NN*HH;
    for (int r = t; r < NN*HH; r += 256) ts[r] = tb[r];
    for (int r = t; r < 4*NN*3; r += 256) ((float*)evl)[r] = g_ev[(b*NN + i0)*NN*3 + r];
    __syncthreads();
    const __half2* m0 = (const __half2*)(g_maskh + (size_t)((b*NN + i0 + rg)*NN)*HH);
    float a00 = 0.f, a01 = 0.f, a10 = 0.f, a11 = 0.f, a20 = 0.f, a21 = 0.f;
    #pragma unroll 4
    for (int j = 0; j < NN; j++){
        float2 tv = *(const float2*)&ts[j*HH + 2*h2];
        float2 mq = __half22float2(m0[j*64 + h2]);
        float m0v = mq.x * tv.x, m1v = mq.y * tv.y;
        float e0 = evl[rg][j*3+0], e1 = evl[rg][j*3+1], e2 = evl[rg][j*3+2];
        a00 = fmaf(m0v, e0, a00); a01 = fmaf(m1v, e0, a01);
        a10 = fmaf(m0v, e1, a10); a11 = fmaf(m1v, e1, a11);
        a20 = fmaf(m0v, e2, a20); a21 = fmaf(m1v, e2, a21);
    }
    int base = (b*NN + i0 + rg)*3;
    *(float2*)&g_v[(base + 0)*HH + 2*h2] = make_float2(a00, a01);
    *(float2*)&g_v[(base + 1)*HH + 2*h2] = make_float2(a10, a11);
    *(float2*)&g_v[(base + 2)*HH + 2*h2] = make_float2(a20, a21);
}

// ---------------- K4b: vq = v@Wq, vk = v@Wk (8 rows per block) ----------------
__global__ void k_vqk(const float* __restrict__ Wq, const float* __restrict__ Wk){
    int blk = blockIdx.x;
    int h = threadIdx.x;
    __shared__ float vs[8][HH];
    for (int r = h; r < 8*HH; r += 128) ((float*)vs)[r] = g_v[blk*8*HH + r];
    __syncthreads();
    float aq[8], ak[8];
    #pragma unroll
    for (int r = 0; r < 8; r++){ aq[r] = 0.f; ak[r] = 0.f; }
    #pragma unroll 4
    for (int k = 0; k < HH; k++){
        float wq = Wq[k*HH + h];
        float wk = Wk[k*HH + h];
        #pragma unroll
        for (int r = 0; r < 8; r++){
            float v = vs[r][k];
            aq[r] = fmaf(v, wq, aq[r]);
            ak[r] = fmaf(v, wk, ak[r]);
        }
    }
    #pragma unroll
    for (int r = 0; r < 8; r++){
        g_vq[(blk*8 + r)*HH + h] = aq[r];
        g_vk[(blk*8 + r)*HH + h] = ak[r];
    }
}

// ---------------- K5: directional MLP (512 threads, LDS.64 fragment loads) ----------------
// smem words: Ah 128*136=17408 | Bh 256*40=10240 | b1s 256 | b2s 128 = 28032 (112128 B)
#define SMEM_DIR_BYTES (28032*4)
__global__ void __launch_bounds__(512) k_dir(const float* __restrict__ bd1,
                                             const float* __restrict__ bd2){
    extern __shared__ unsigned smu[];
    unsigned* Ah = smu;                          // [e][kp], stride ASTR, k-pair permuted
    unsigned* Bh = smu + 17408;                  // staging [n][kp'], stride BSTR, permuted
    float* b1s = (float*)(smu + 27648);
    float* b2s = (float*)(smu + 27904);
    // pre-GEMM scratch overlaps Bh (dead before first staging store)
    float* eas = (float*)(Bh);                   // 128
    float* evs = (float*)(Bh + 128);             // 384
    float* vks = (float*)(Bh + 512);             // 768
    float* Ps  = (float*)(Bh + 1280);            // 1536

    int t = threadIdx.x, lane = t & 31, wid = t >> 5;
    int g = lane >> 2, tig = lane & 3;
    int bi0 = blockIdx.x * 2, bbase = bi0 & ~63;

    if (t < 256) b1s[t] = bd1[t];
    if (t < 128) b2s[t] = bd2[t];
    if (t < 128) eas[t] = g_ea[bi0*64 + t];
    for (int r = t; r < 384;  r += 512) evs[r] = g_ev[bi0*192 + r];
    for (int r = t; r < 768;  r += 512) vks[r] = g_vk[bi0*384 + r];
    for (int r = t; r < 1536; r += 512) Ps [r] = g_P [bi0*768 + r];
    __syncthreads();

    // build dir3 (scaled 1/64) -> Ah kp 0..63 (permuted positions)
    {
        int kp3 = t & 63, grp = t >> 6;          // grp 0..7
        int i  = grp & 1, jq = grp >> 1;         // jq 0..3: 16 j each
        int kk = 2*kp3;
        int astk = ast(kp3);
        float u0 = vks[i*384 + kk],     u1 = vks[i*384 + 128 + kk], u2 = vks[i*384 + 256 + kk];
        float w0 = vks[i*384 + kk + 1], w1 = vks[i*384 + 129 + kk], w2 = vks[i*384 + 257 + kk];
        for (int jj = 0; jj < 16; jj++){
            int j = jq*16 + jj;
            int e = i*64 + j;
            float ea = eas[e] * 0.015625f;
            const float* vq = g_vq + (bbase + j)*384 + kk;
            float2 q0 = *(const float2*)vq;
            float2 q1 = *(const float2*)(vq + 128);
            float2 q2 = *(const float2*)(vq + 256);
            float f0 = (q0.x*u0 + q1.x*u1 + q2.x*u2) * ea;
            float f1 = (q0.y*w0 + q1.y*w1 + q2.y*w2) * ea;
            Ah[e*ASTR + astk] = half_pack(f0, f1);
        }
    }

    int m0 = (wid & 3) * 32;                     // 4 m-groups x 32 rows
    int nh = wid >> 2;                           // 4 n-groups

    // init acc1 with dir2 low-rank contribution (GEMM1 cols nh*64 .. +63)
    float acc1[2][8][4];
    #pragma unroll
    for (int ms = 0; ms < 2; ms++){
        int ea_r = m0 + ms*16 + g;
        int eb_r = ea_r + 8;
        int ia = ea_r >> 6, ib = eb_r >> 6;
        float ca0 = evs[ea_r*3], ca1 = evs[ea_r*3+1], ca2 = evs[ea_r*3+2];
        float cb0 = evs[eb_r*3], cb1 = evs[eb_r*3+1], cb2 = evs[eb_r*3+2];
        float wa = eas[ea_r], wb = eas[eb_r];
        const float* Pa = Ps + ia*768;
        const float* Pb = Ps + ib*768;
        #pragma unroll
        for (int nt = 0; nt < 8; nt++){
            int c0 = nh*64 + nt*8 + 2*tig;
            acc1[ms][nt][0] = wa * (ca0*Pa[c0]   + ca1*Pa[256+c0]   + ca2*Pa[512+c0]);
            acc1[ms][nt][1] = wa * (ca0*Pa[c0+1] + ca1*Pa[256+c0+1] + ca2*Pa[512+c0+1]);
            acc1[ms][nt][2] = wb * (cb0*Pb[c0]   + cb1*Pb[256+c0]   + cb2*Pb[512+c0]);
            acc1[ms][nt][3] = wb * (cb0*Pb[c0+1] + cb1*Pb[256+c0+1] + cb2*Pb[512+c0+1]);
        }
    }

    // ===== GEMM1 (dir3 half): K=128, 2 chunks, single buffer + reg prefetch =====
    {
        uint4 pf[4];
        #pragma unroll
        for (int q = 0; q < 4; q++){
            int r = t + q*512;
            pf[q] = *(const uint4*)&gW1h3[(r>>3)*64 + (r&7)*4];
        }
        __syncthreads();                 // scratch reads (build + init acc1) done
        #pragma unroll
        for (int q = 0; q < 4; q++){
            int r = t + q*512;
            *(uint4*)&Bh[(r>>3)*BSTR + (r&7)*4] = pf[q];
        }
        __syncthreads();
        for (int c = 0; c < 2; c++){
            if (c == 0){
                #pragma unroll
                for (int q = 0; q < 4; q++){
                    int r = t + q*512;
                    pf[q] = *(const uint4*)&gW1h3[(r>>3)*64 + 32 + (r&7)*4];
                }
            }
            #pragma unroll
            for (int ksl = 0; ksl < 4; ksl++){
                int kp0 = c*32 + ksl*8;
                int kb  = ksl*8;
                unsigned ah[2][4];
                #pragma unroll
                for (int ms = 0; ms < 2; ms++){
                    int r0 = m0 + ms*16;
                    uint2 pa0 = *(const uint2*)&Ah[(r0+g  )*ASTR + kp0 + 2*tig];
                    uint2 pa1 = *(const uint2*)&Ah[(r0+g+8)*ASTR + kp0 + 2*tig];
                    ah[ms][0] = pa0.x; ah[ms][1] = pa1.x;
                    ah[ms][2] = pa0.y; ah[ms][3] = pa1.y;
                }
                #pragma unroll
                for (int nt = 0; nt < 8; nt++){
                    int n0 = nh*64 + nt*8;
                    uint2 pb = *(const uint2*)&Bh[(n0+g)*BSTR + kb + 2*tig];
                    mma16h(acc1[0][nt], ah[0], pb.x, pb.y);
                    mma16h(acc1[1][nt], ah[1], pb.x, pb.y);
                }
            }
            __syncthreads();
            if (c == 0){
                #pragma unroll
                for (int q = 0; q < 4; q++){
                    int r = t + q*512;
                    *(uint4*)&Bh[(r>>3)*BSTR + (r&7)*4] = pf[q];
                }
                __syncthreads();
            }
        }
    }

    // epilogue1: h1 = silu(D1 + b1) packed back into Ah (permuted positions)
    #pragma unroll
    for (int ms = 0; ms < 2; ms++){
        #pragma unroll
        for (int nt = 0; nt < 8; nt++){
            int c0 = nh*64 + nt*8 + 2*tig;
            int kph = ast(c0 >> 1);
            int r0 = m0 + ms*16 + g;
            float y0 = silu_f(acc1[ms][nt][0] + b1s[c0]);
            float y1 = silu_f(acc1[ms][nt][1] + b1s[c0+1]);
            Ah[r0*ASTR + kph] = half_pack(y0, y1);
            float y2 = silu_f(acc1[ms][nt][2] + b1s[c0]);
            float y3 = silu_f(acc1[ms][nt][3] + b1s[c0+1]);
            Ah[(r0+8)*ASTR + kph] = half_pack(y2, y3);
        }
    }

    // ===== GEMM2: K=256, 4 chunks, single buffer + reg prefetch =====
    float acc2[2][4][4];
    #pragma unroll
    for (int ms = 0; ms < 2; ms++)
        #pragma unroll
        for (int nt = 0; nt < 4; nt++)
            #pragma unroll
            for (int q = 0; q < 4; q++) acc2[ms][nt][q] = 0.f;

    {
        uint4 pf[2];
        #pragma unroll
        for (int q = 0; q < 2; q++){
            int r = t + q*512;
            pf[q] = *(const uint4*)&gW2h[(r>>3)*128 + (r&7)*4];
        }
        __syncthreads();                 // epilogue1 Ah writes done; last GEMM1 Bh reads done
        #pragma unroll
        for (int q = 0; q < 2; q++){
            int r = t + q*512;
            *(uint4*)&Bh[(r>>3)*BSTR + (r&7)*4] = pf[q];
        }
        __syncthreads();
        for (int c = 0; c < 4; c++){
            if (c + 1 < 4){
                #pragma unroll
                for (int q = 0; q < 2; q++){
                    int r = t + q*512;
                    pf[q] = *(const uint4*)&gW2h[(r>>3)*128 + (c+1)*32 + (r&7)*4];
                }
            }
            #pragma unroll
            for (int ksl = 0; ksl < 4; ksl++){
                int kp0 = c*32 + ksl*8;
                int kb  = ksl*8;
                unsigned ah[2][4];
                #pragma unroll
                for (int ms = 0; ms < 2; ms++){
                    int r0 = m0 + ms*16;
                    uint2 pa0 = *(const uint2*)&Ah[(r0+g  )*ASTR + kp0 + 2*tig];
                    uint2 pa1 = *(const uint2*)&Ah[(r0+g+8)*ASTR + kp0 + 2*tig];
                    ah[ms][0] = pa0.x; ah[ms][1] = pa1.x;
                    ah[ms][2] = pa0.y; ah[ms][3] = pa1.y;
                }
                #pragma unroll
                for (int nt = 0; nt < 4; nt++){
                    int n0 = nh*32 + nt*8;
                    uint2 pb = *(const uint2*)&Bh[(n0+g)*BSTR + kb + 2*tig];
                    mma16h(acc2[0][nt], ah[0], pb.x, pb.y);
                    mma16h(acc2[1][nt], ah[1], pb.x, pb.y);
                }
            }
            __syncthreads();
            if (c + 1 < 4){
                #pragma unroll
                for (int q = 0; q < 2; q++){
                    int r = t + q*512;
                    *(uint4*)&Bh[(r>>3)*BSTR + (r&7)*4] = pf[q];
                }
                __syncthreads();
            }
        }
    }

    // epilogue2: maskh *= silu(D2 + b2)  (cols nh*32..+31)
    #pragma unroll
    for (int ms = 0; ms < 2; ms++){
        #pragma unroll
        for (int nt = 0; nt < 4; nt++){
            int c0 = nh*32 + nt*8 + 2*tig;
            int e0 = m0 + ms*16 + g;
            size_t base0 = ((size_t)(bi0*64 + e0))*128 + c0;
            __half2* p0 = (__half2*)&g_maskh[base0];
            float2 mv = __half22float2(*p0);
            mv.x *= silu_f(acc2[ms][nt][0] + b2s[c0]);
            mv.y *= silu_f(acc2[ms][nt][1] + b2s[c0+1]);
            *p0 = __float22half2_rn(mv);
            __half2* p1 = (__half2*)&g_maskh[base0 + 8*128];
            float2 mw = __half22float2(*p1);
            mw.x *= silu_f(acc2[ms][nt][2] + b2s[c0]);
            mw.y *= silu_f(acc2[ms][nt][3] + b2s[c0+1]);
            *p1 = __float22half2_rn(mw);
        }
    }
}

// ---------------- K7: readout ----------------
__global__ void k_out(const int* __restrict__ z, const float* __restrict__ Wo,
                      const float* __restrict__ bo, float* __restrict__ out){
    int b = blockIdx.x, h = threadIdx.x;
    __shared__ float red[4];
    float acc = 0.f;
    for (int i = 0; i < NN; i++)
        if (z[b*NN + i] != 0) acc += g_s[(b*NN + i)*HH + h];
    float part = acc * Wo[h];
    float tot = blkred128(part, red);
    if (h == 0) out[b] = tot + bo[0];
}

// ---------------- launch ----------------
extern "C" void kernel_launch(void* const* d_in, const int* in_sizes, int n_in,
                              void* d_out, int out_size){
    const int*   z      = (const int*)  d_in[0];
    const float* pos    = (const float*)d_in[1];
    const float* emb_w  = (const float*)d_in[2];
    const float* emb2_w = (const float*)d_in[3];
    const float* Wef    = (const float*)d_in[4];
    const float* bef    = (const float*)d_in[5];
    const float* Ws2v   = (const float*)d_in[6];
    const float* bs2v   = (const float*)d_in[7];
    const float* Wq     = (const float*)d_in[8];
    const float* Wk     = (const float*)d_in[9];
    const float* Wd1    = (const float*)d_in[10];
    const float* bd1    = (const float*)d_in[11];
    const float* Wd2    = (const float*)d_in[12];
    const float* bd2    = (const float*)d_in[13];
    const float* Wint   = (const float*)d_in[14];
    const float* bint   = (const float*)d_in[15];
    const float* Wo     = (const float*)d_in[16];
    const float* bo     = (const float*)d_in[17];
    float* out = (float*)d_out;

    cudaFuncSetAttribute(k_dir, cudaFuncAttributeMaxDynamicSharedMemorySize, SMEM_DIR_BYTES);

    k_whalf<<<384, 128>>>(Wd1, Wd2);
    k_geom <<<BB*NN, 256>>>(z, pos, Wef, bef);
    k_embed<<<BB*NN, 128>>>(z, emb_w, emb2_w);
    k_gather<<<BB*NN/8, 256>>>(0);               // s += mask @ sn
    k_lin  <<<BB*NN/4, 128>>>(Ws2v, bs2v, 0);    // t = silu(LN(s@Ws2v+b))
    k_v    <<<BB*NN/4, 256>>>();
    k_vqk  <<<BB*NN*3/8, 128>>>(Wq, Wk);
    k_p    <<<BB*NN, 256>>>(Wd1);
    k_dir  <<<BB*NN/2, 512, SMEM_DIR_BYTES>>>(bd1, bd2);
    for (int l = 0; l < 3; l++){
        k_lin   <<<BB*NN/4, 128>>>(Wint + l*HH*HH, bint + l*HH, 1);  // sl
        k_gather<<<BB*NN/8, 256>>>(1);                                // s += mask @ sl
    }
    k_out<<<BB, 128>>>(z, Wo, bo, out);
}